// round 15
// baseline (speedup 1.0000x reference)
#include <cuda_runtime.h>
#include <cuda_bf16.h>
#include <cuda_pipeline.h>
#include <math.h>

constexpr float kConfidence = 0.9f;
constexpr float kSmoothing  = 0.1f;
constexpr int   WARPS_PER_BLOCK = 8;   // one warp per row

// Preprocessed weights in bf16: g_pad[t*C + c] = 0.1*conf[t][src(c)]/sum(conf[t]),
// 0 at c==t. Row stride C=1000 bf16 = 2000 B.
__device__ __nv_bfloat16 g_pad[1024 * 1024];

// One block per class t. Block 0 also zeroes the output accumulator.
__global__ void __launch_bounds__(256)
prep_conf_kernel(const float* __restrict__ confusion, float* __restrict__ out, int C)
{
    const int t   = blockIdx.x;
    const int tid = threadIdx.x;
    if (t == 0 && tid == 0) out[0] = 0.0f;

    const float* row = confusion + (size_t)t * (C - 1);

    float acc = 0.f;
    for (int j = tid; j < C - 1; j += 256) acc += __ldg(row + j);

    const unsigned FULL = 0xffffffffu;
#pragma unroll
    for (int off = 16; off; off >>= 1) acc += __shfl_down_sync(FULL, acc, off);

    __shared__ float sw[8];
    __shared__ float s_invA;
    if ((tid & 31) == 0) sw[tid >> 5] = acc;
    __syncthreads();
    if (tid == 0) {
        float tot = sw[0] + sw[1] + sw[2] + sw[3] + sw[4] + sw[5] + sw[6] + sw[7];
        s_invA = kSmoothing / tot;
    }
    __syncthreads();
    const float invA = s_invA;

    __nv_bfloat162* dst2 = reinterpret_cast<__nv_bfloat162*>(g_pad + (size_t)t * C);
    const int npairs = C >> 1;   // 500
    for (int i = tid; i < npairs; i += 256) {
        const int c0 = 2 * i, c1 = 2 * i + 1;
        const float v0 = (c0 == t) ? 0.f : __ldg(row + (c0 - (c0 > t))) * invA;
        const float v1 = (c1 == t) ? 0.f : __ldg(row + (c1 - (c1 > t))) * invA;
        dst2[i] = __floats2bfloat162_rn(v0, v1);
    }

    __threadfence();
#if __CUDA_ARCH__ >= 900
    cudaTriggerProgrammaticLaunchCompletion();
#endif
}

// Consume one group of 4 classes: pred float4 + weights bf16x4 (as uint2).
__device__ __forceinline__ void consume4(const float4 p, const uint2 c,
                                         float& s0, float& s1, float& d0, float& d1)
{
    s0 += __expf(p.x) + __expf(p.y);
    s1 += __expf(p.z) + __expf(p.w);
    const __nv_bfloat162 c01 = *reinterpret_cast<const __nv_bfloat162*>(&c.x);
    const __nv_bfloat162 c23 = *reinterpret_cast<const __nv_bfloat162*>(&c.y);
    const float2 f01 = __bfloat1622float2(c01);
    const float2 f23 = __bfloat1622float2(c23);
    d0 = fmaf(f01.x, p.x, fmaf(f01.y, p.y, d0));
    d1 = fmaf(f23.x, p.z, fmaf(f23.y, p.w, d1));
}

template <int CN>
__global__ void __launch_bounds__(256, 4)
row_loss_kernel(const float* __restrict__ pred,
                const int*   __restrict__ tgt_raw,
                float* __restrict__ out,
                int Bn, float invB)
{
    constexpr int NVEC = CN / 4;                  // 250
    constexpr int FULL_ITERS = NVEC / 32;         // 7
    constexpr int TAIL = NVEC - FULL_ITERS * 32;  // 26
    constexpr int NITER = FULL_ITERS + 1;         // 8

    // Per-thread pred staging via cp.async: MLP=8 with zero register cost.
    // Each thread writes and reads ONLY its own [wid][k][lane] slots.
    __shared__ float4 s_pred[WARPS_PER_BLOCK][NITER][32];   // 32 KB

    const int tid  = threadIdx.x;
    const int wid  = tid >> 5;
    const int lane = tid & 31;
    const int row  = blockIdx.x * WARPS_PER_BLOCK + wid;

    // int64 vs int32 target detection (odd 32-bit words all zero => int64).
    const bool is64 = ((tgt_raw[1] | tgt_raw[3] | tgt_raw[5] | tgt_raw[7]) == 0);

#if __CUDA_ARCH__ >= 900
    cudaGridDependencySynchronize();
#endif

    float row_loss = 0.0f;

    if (row < Bn) {
        const int t = is64 ? tgt_raw[2 * row] : tgt_raw[row];

        const float4* prow = reinterpret_cast<const float4*>(pred + (size_t)row * CN);
        const uint2*  crow = reinterpret_cast<const uint2*>(g_pad + (size_t)t * CN);

        // Early target-pred load: overlaps everything below.
        float pt = 0.0f;
        if (lane == 0) pt = __ldcs(pred + (size_t)row * CN + t);

        // Issue ALL pred copies async (global -> smem, L1-bypassing .cg path).
#pragma unroll
        for (int k = 0; k < FULL_ITERS; k++) {
            __pipeline_memcpy_async(&s_pred[wid][k][lane], prow + lane + k * 32, 16);
            __pipeline_commit();
        }
        if (lane < TAIL) {
            __pipeline_memcpy_async(&s_pred[wid][FULL_ITERS][lane],
                                    prow + lane + FULL_ITERS * 32, 16);
            __pipeline_commit();
        }

        // Meanwhile stage all weights in registers (small, mostly L2-hits).
        uint2 w[NITER];
#pragma unroll
        for (int k = 0; k < FULL_ITERS; k++)
            w[k] = __ldg(crow + lane + k * 32);
        w[FULL_ITERS] = (lane < TAIL) ? __ldg(crow + lane + FULL_ITERS * 32)
                                      : make_uint2(0u, 0u);

        // Wait for this thread's async copies, then consume from smem.
        __pipeline_wait_prior(0);

        float s0 = 0.f, s1 = 0.f, d0 = 0.f, d1 = 0.f;
#pragma unroll
        for (int k = 0; k < FULL_ITERS; k++)
            consume4(s_pred[wid][k][lane], w[k], s0, s1, d0, d1);
        {
            const float4 pv = (lane < TAIL)
                ? s_pred[wid][FULL_ITERS][lane]
                : make_float4(-1e30f, -1e30f, -1e30f, -1e30f);   // exp -> 0
            consume4(pv, w[FULL_ITERS], s0, s1, d0, d1);
        }

        float s   = s0 + s1;
        float dot = d0 + d1;

        const unsigned FULL = 0xffffffffu;
#pragma unroll
        for (int off = 16; off; off >>= 1) {
            s   += __shfl_down_sync(FULL, s,   off);
            dot += __shfl_down_sync(FULL, dot, off);
        }

        if (lane == 0)
            row_loss = __logf(s) - kConfidence * pt - dot;   // dot pre-scaled by 0.1/A
    }

    __shared__ float sh[WARPS_PER_BLOCK];
    if (lane == 0) sh[wid] = row_loss;
    __syncthreads();

    if (tid == 0) {
        float acc = sh[0];
#pragma unroll
        for (int w2 = 1; w2 < WARPS_PER_BLOCK; w2++) acc += sh[w2];
        atomicAdd(out, acc * invB);
    }
}

// Generic fallback for unexpected C (runtime trip count).
__global__ void __launch_bounds__(256, 4)
row_loss_kernel_generic(const float* __restrict__ pred,
                        const int*   __restrict__ tgt_raw,
                        float* __restrict__ out,
                        int Bn, int Cn, float invB)
{
    const int tid  = threadIdx.x;
    const int wid  = tid >> 5;
    const int lane = tid & 31;
    const int row  = blockIdx.x * WARPS_PER_BLOCK + wid;
    const bool is64 = ((tgt_raw[1] | tgt_raw[3] | tgt_raw[5] | tgt_raw[7]) == 0);

    float row_loss = 0.0f;
    if (row < Bn) {
        const int t = is64 ? tgt_raw[2 * row] : tgt_raw[row];
        const float4* prow = reinterpret_cast<const float4*>(pred + (size_t)row * Cn);
        const uint2*  crow = reinterpret_cast<const uint2*>(g_pad + (size_t)t * Cn);
        const int nvec = Cn >> 2;
        float s0 = 0.f, s1 = 0.f, d0 = 0.f, d1 = 0.f;
#pragma unroll 4
        for (int j = lane; j < nvec; j += 32) {
            const float4 p4 = __ldg(prow + j);
            const uint2  c4 = __ldg(crow + j);
            consume4(p4, c4, s0, s1, d0, d1);
        }
        float s = s0 + s1, dot = d0 + d1;
        const unsigned FULL = 0xffffffffu;
#pragma unroll
        for (int off = 16; off; off >>= 1) {
            s   += __shfl_down_sync(FULL, s,   off);
            dot += __shfl_down_sync(FULL, dot, off);
        }
        if (lane == 0) {
            const float pt = __ldg(pred + (size_t)row * Cn + t);
            row_loss = __logf(s) - kConfidence * pt - dot;
        }
    }
    __shared__ float sh[WARPS_PER_BLOCK];
    if (lane == 0) sh[wid] = row_loss;
    __syncthreads();
    if (tid == 0) {
        float acc = sh[0];
#pragma unroll
        for (int w = 1; w < WARPS_PER_BLOCK; w++) acc += sh[w];
        atomicAdd(out, acc * invB);
    }
}

extern "C" void kernel_launch(void* const* d_in, const int* in_sizes, int n_in,
                              void* d_out, int out_size) {
    const float* pred      = (const float*)d_in[0];
    const int*   tgt_raw   = (const int*)d_in[1];
    const float* confusion = (const float*)d_in[2];

    const int Bn = in_sizes[1];          // 32768 rows
    const int Cn = in_sizes[0] / Bn;     // 1000 classes

    float* out = (float*)d_out;
    prep_conf_kernel<<<Cn, 256>>>(confusion, out, Cn);

    const float invB = 1.0f / (float)Bn;

    if (Cn == 1000) {
        const int grid = (Bn + WARPS_PER_BLOCK - 1) / WARPS_PER_BLOCK;   // 4096
        cudaLaunchConfig_t cfg = {};
        cfg.gridDim  = dim3(grid);
        cfg.blockDim = dim3(256);
        cfg.dynamicSmemBytes = 0;
        cfg.stream = 0;
        cudaLaunchAttribute attrs[1];
        attrs[0].id = cudaLaunchAttributeProgrammaticStreamSerialization;
        attrs[0].val.programmaticStreamSerializationAllowed = 1;
        cfg.attrs = attrs;
        cfg.numAttrs = 1;

        cudaError_t e = cudaLaunchKernelEx(&cfg, row_loss_kernel<1000>,
                                           pred, tgt_raw, out, Bn, invB);
        if (e != cudaSuccess) {
            (void)cudaGetLastError();   // clear, fall back to plain launch
            row_loss_kernel<1000><<<grid, 256>>>(pred, tgt_raw, out, Bn, invB);
        }
    } else {
        const int grid = (Bn + WARPS_PER_BLOCK - 1) / WARPS_PER_BLOCK;
        row_loss_kernel_generic<<<grid, 256>>>(pred, tgt_raw, out, Bn, Cn, invB);
    }
}

// round 16
// speedup vs baseline: 1.0020x; 1.0020x over previous
#include <cuda_runtime.h>
#include <cuda_bf16.h>
#include <math.h>

constexpr float kConfidence = 0.9f;
constexpr float kSmoothing  = 0.1f;
constexpr int   WARPS_PER_BLOCK = 8;   // one warp per row

// Preprocessed weights in bf16: g_pad[t*C + c] = 0.1*conf[t][src(c)]/sum(conf[t]),
// 0 at c==t. Row stride C=1000 bf16 = 2000 B.
__device__ __nv_bfloat16 g_pad[1024 * 1024];

// One block per class t. Block 0 also zeroes the output accumulator.
__global__ void __launch_bounds__(256)
prep_conf_kernel(const float* __restrict__ confusion, float* __restrict__ out, int C)
{
    const int t   = blockIdx.x;
    const int tid = threadIdx.x;
    if (t == 0 && tid == 0) out[0] = 0.0f;

    const float* row = confusion + (size_t)t * (C - 1);

    float acc = 0.f;
    for (int j = tid; j < C - 1; j += 256) acc += __ldg(row + j);

    const unsigned FULL = 0xffffffffu;
#pragma unroll
    for (int off = 16; off; off >>= 1) acc += __shfl_down_sync(FULL, acc, off);

    __shared__ float sw[8];
    __shared__ float s_invA;
    if ((tid & 31) == 0) sw[tid >> 5] = acc;
    __syncthreads();
    if (tid == 0) {
        float tot = sw[0] + sw[1] + sw[2] + sw[3] + sw[4] + sw[5] + sw[6] + sw[7];
        s_invA = kSmoothing / tot;
    }
    __syncthreads();
    const float invA = s_invA;

    __nv_bfloat162* dst2 = reinterpret_cast<__nv_bfloat162*>(g_pad + (size_t)t * C);
    const int npairs = C >> 1;   // 500
    for (int i = tid; i < npairs; i += 256) {
        const int c0 = 2 * i, c1 = 2 * i + 1;
        const float v0 = (c0 == t) ? 0.f : __ldg(row + (c0 - (c0 > t))) * invA;
        const float v1 = (c1 == t) ? 0.f : __ldg(row + (c1 - (c1 > t))) * invA;
        dst2[i] = __floats2bfloat162_rn(v0, v1);
    }

    __threadfence();
#if __CUDA_ARCH__ >= 900
    cudaTriggerProgrammaticLaunchCompletion();
#endif
}

// Consume one group of 4 classes: pred float4 + weights bf16x4 (as uint2).
__device__ __forceinline__ void consume4(const float4 p, const uint2 c,
                                         float& s0, float& s1, float& d0, float& d1)
{
    s0 += __expf(p.x) + __expf(p.y);
    s1 += __expf(p.z) + __expf(p.w);
    const __nv_bfloat162 c01 = *reinterpret_cast<const __nv_bfloat162*>(&c.x);
    const __nv_bfloat162 c23 = *reinterpret_cast<const __nv_bfloat162*>(&c.y);
    const float2 f01 = __bfloat1622float2(c01);
    const float2 f23 = __bfloat1622float2(c23);
    d0 = fmaf(f01.x, p.x, fmaf(f01.y, p.y, d0));
    d1 = fmaf(f23.x, p.z, fmaf(f23.y, p.w, d1));
}

// R7 loop verbatim (best measured row kernel: 25.63us): depth-2 pipeline,
// plain __ldg on both streams, occ-4 / 64-reg budget.
template <int CN>
__global__ void __launch_bounds__(256, 4)
row_loss_kernel(const float* __restrict__ pred,
                const int*   __restrict__ tgt_raw,
                float* __restrict__ out,
                int Bn, float invB)
{
    constexpr int NVEC = CN / 4;                  // 250
    constexpr int FULL_ITERS = NVEC / 32;         // 7
    constexpr int TAIL = NVEC - FULL_ITERS * 32;  // 26

    const int tid  = threadIdx.x;
    const int wid  = tid >> 5;
    const int lane = tid & 31;
    const int row  = blockIdx.x * WARPS_PER_BLOCK + wid;

    // int64 vs int32 target detection (odd 32-bit words all zero => int64).
    const bool is64 = ((tgt_raw[1] | tgt_raw[3] | tgt_raw[5] | tgt_raw[7]) == 0);

#if __CUDA_ARCH__ >= 900
    cudaGridDependencySynchronize();   // PDL gate: weights published by prep
#endif

    float row_loss = 0.0f;

    if (row < Bn) {
        const int t = is64 ? tgt_raw[2 * row] : tgt_raw[row];

        const float4* prow = reinterpret_cast<const float4*>(pred + (size_t)row * CN);
        const uint2*  crow = reinterpret_cast<const uint2*>(g_pad + (size_t)t * CN);

        // Early target-pred load: overlaps the main stream.
        float pt = 0.0f;
        if (lane == 0) pt = __ldg(pred + (size_t)row * CN + t);

        float s0 = 0.f, s1 = 0.f, d0 = 0.f, d1 = 0.f;

        // Depth-2 software pipeline: prefetch next pair before consuming current.
        float4 p_cur = __ldg(prow + lane);
        uint2  c_cur = __ldg(crow + lane);

#pragma unroll
        for (int k = 1; k < FULL_ITERS; k++) {
            const int j = lane + k * 32;
            const float4 p_nxt = __ldg(prow + j);
            const uint2  c_nxt = __ldg(crow + j);
            consume4(p_cur, c_cur, s0, s1, d0, d1);
            p_cur = p_nxt;
            c_cur = c_nxt;
        }
        // prefetch predicated tail, then consume last full + tail (branch-free)
        const int jt = lane + FULL_ITERS * 32;
        float4 p_t = make_float4(-1e30f, -1e30f, -1e30f, -1e30f);  // exp -> 0
        uint2  c_t = make_uint2(0u, 0u);
        if (lane < TAIL) {
            p_t = __ldg(prow + jt);
            c_t = __ldg(crow + jt);
        }
        consume4(p_cur, c_cur, s0, s1, d0, d1);
        consume4(p_t,   c_t,   s0, s1, d0, d1);

        float s   = s0 + s1;
        float dot = d0 + d1;

        const unsigned FULL = 0xffffffffu;
#pragma unroll
        for (int off = 16; off; off >>= 1) {
            s   += __shfl_down_sync(FULL, s,   off);
            dot += __shfl_down_sync(FULL, dot, off);
        }

        if (lane == 0)
            row_loss = __logf(s) - kConfidence * pt - dot;   // dot pre-scaled by 0.1/A
    }

    __shared__ float sh[WARPS_PER_BLOCK];
    if (lane == 0) sh[wid] = row_loss;
    __syncthreads();

    if (tid == 0) {
        float acc = sh[0];
#pragma unroll
        for (int w = 1; w < WARPS_PER_BLOCK; w++) acc += sh[w];
        atomicAdd(out, acc * invB);
    }
}

// Generic fallback for unexpected C (runtime trip count).
__global__ void __launch_bounds__(256, 4)
row_loss_kernel_generic(const float* __restrict__ pred,
                        const int*   __restrict__ tgt_raw,
                        float* __restrict__ out,
                        int Bn, int Cn, float invB)
{
    const int tid  = threadIdx.x;
    const int wid  = tid >> 5;
    const int lane = tid & 31;
    const int row  = blockIdx.x * WARPS_PER_BLOCK + wid;
    const bool is64 = ((tgt_raw[1] | tgt_raw[3] | tgt_raw[5] | tgt_raw[7]) == 0);

    float row_loss = 0.0f;
    if (row < Bn) {
        const int t = is64 ? tgt_raw[2 * row] : tgt_raw[row];
        const float4* prow = reinterpret_cast<const float4*>(pred + (size_t)row * Cn);
        const uint2*  crow = reinterpret_cast<const uint2*>(g_pad + (size_t)t * Cn);
        const int nvec = Cn >> 2;
        float s0 = 0.f, s1 = 0.f, d0 = 0.f, d1 = 0.f;
#pragma unroll 4
        for (int j = lane; j < nvec; j += 32) {
            const float4 p4 = __ldg(prow + j);
            const uint2  c4 = __ldg(crow + j);
            consume4(p4, c4, s0, s1, d0, d1);
        }
        float s = s0 + s1, dot = d0 + d1;
        const unsigned FULL = 0xffffffffu;
#pragma unroll
        for (int off = 16; off; off >>= 1) {
            s   += __shfl_down_sync(FULL, s,   off);
            dot += __shfl_down_sync(FULL, dot, off);
        }
        if (lane == 0) {
            const float pt = __ldg(pred + (size_t)row * Cn + t);
            row_loss = __logf(s) - kConfidence * pt - dot;
        }
    }
    __shared__ float sh[WARPS_PER_BLOCK];
    if (lane == 0) sh[wid] = row_loss;
    __syncthreads();
    if (tid == 0) {
        float acc = sh[0];
#pragma unroll
        for (int w = 1; w < WARPS_PER_BLOCK; w++) acc += sh[w];
        atomicAdd(out, acc * invB);
    }
}

extern "C" void kernel_launch(void* const* d_in, const int* in_sizes, int n_in,
                              void* d_out, int out_size) {
    const float* pred      = (const float*)d_in[0];
    const int*   tgt_raw   = (const int*)d_in[1];
    const float* confusion = (const float*)d_in[2];

    const int Bn = in_sizes[1];          // 32768 rows
    const int Cn = in_sizes[0] / Bn;     // 1000 classes

    float* out = (float*)d_out;
    prep_conf_kernel<<<Cn, 256>>>(confusion, out, Cn);

    const float invB = 1.0f / (float)Bn;
    const int grid = (Bn + WARPS_PER_BLOCK - 1) / WARPS_PER_BLOCK;   // 4096

    if (Cn == 1000) {
        // PDL launch: row kernel overlaps prep's tail; weight reads are gated
        // in-kernel by cudaGridDependencySynchronize().
        cudaLaunchConfig_t cfg = {};
        cfg.gridDim  = dim3(grid);
        cfg.blockDim = dim3(256);
        cfg.dynamicSmemBytes = 0;
        cfg.stream = 0;
        cudaLaunchAttribute attrs[1];
        attrs[0].id = cudaLaunchAttributeProgrammaticStreamSerialization;
        attrs[0].val.programmaticStreamSerializationAllowed = 1;
        cfg.attrs = attrs;
        cfg.numAttrs = 1;

        cudaError_t e = cudaLaunchKernelEx(&cfg, row_loss_kernel<1000>,
                                           pred, tgt_raw, out, Bn, invB);
        if (e != cudaSuccess) {
            (void)cudaGetLastError();   // clear, fall back to plain launch
            row_loss_kernel<1000><<<grid, 256>>>(pred, tgt_raw, out, Bn, invB);
        }
    } else {
        row_loss_kernel_generic<<<grid, 256>>>(pred, tgt_raw, out, Bn, Cn, invB);
    }
}

// round 17
// speedup vs baseline: 1.1152x; 1.1130x over previous
#include <cuda_runtime.h>
#include <cuda_bf16.h>
#include <math.h>

constexpr float kConfidence = 0.9f;
constexpr float kSmoothing  = 0.1f;
constexpr int   WARPS_PER_BLOCK = 8;   // one warp per row

// Preprocessed weights in bf16: g_pad[t*C + c] = 0.1*conf[t][src(c)]/sum(conf[t]),
// 0 at c==t. Row stride C=1000 bf16 = 2000 B.
__device__ __nv_bfloat16 g_pad[1024 * 1024];

// One block per class t. Single global read pass: confusion row cached in smem.
// Block 0 also zeroes the output accumulator.
__global__ void __launch_bounds__(256)
prep_conf_kernel(const float* __restrict__ confusion, float* __restrict__ out, int C)
{
    __shared__ float s_row[1024];      // C-1 <= 1023 floats
    const int t   = blockIdx.x;
    const int tid = threadIdx.x;
    if (t == 0 && tid == 0) out[0] = 0.0f;

    const float* row = confusion + (size_t)t * (C - 1);

    // One coalesced read pass: accumulate sum while caching into smem.
    float acc = 0.f;
    for (int j = tid; j < C - 1; j += 256) {
        const float v = __ldg(row + j);
        s_row[j] = v;
        acc += v;
    }

    const unsigned FULL = 0xffffffffu;
#pragma unroll
    for (int off = 16; off; off >>= 1) acc += __shfl_down_sync(FULL, acc, off);

    __shared__ float sw[8];
    __shared__ float s_invA;
    if ((tid & 31) == 0) sw[tid >> 5] = acc;
    __syncthreads();
    if (tid == 0) {
        float tot = sw[0] + sw[1] + sw[2] + sw[3] + sw[4] + sw[5] + sw[6] + sw[7];
        s_invA = kSmoothing / tot;
    }
    __syncthreads();
    const float invA = s_invA;

    // Write pass from smem (no second global read).
    __nv_bfloat162* dst2 = reinterpret_cast<__nv_bfloat162*>(g_pad + (size_t)t * C);
    const int npairs = C >> 1;   // 500
    for (int i = tid; i < npairs; i += 256) {
        const int c0 = 2 * i, c1 = 2 * i + 1;
        const float v0 = (c0 == t) ? 0.f : s_row[c0 - (c0 > t)] * invA;
        const float v1 = (c1 == t) ? 0.f : s_row[c1 - (c1 > t)] * invA;
        dst2[i] = __floats2bfloat162_rn(v0, v1);
    }

    __threadfence();
#if __CUDA_ARCH__ >= 900
    cudaTriggerProgrammaticLaunchCompletion();
#endif
}

// Consume one group of 4 classes: pred float4 + weights bf16x4 (as uint2).
__device__ __forceinline__ void consume4(const float4 p, const uint2 c,
                                         float& s0, float& s1, float& d0, float& d1)
{
    s0 += __expf(p.x) + __expf(p.y);
    s1 += __expf(p.z) + __expf(p.w);
    const __nv_bfloat162 c01 = *reinterpret_cast<const __nv_bfloat162*>(&c.x);
    const __nv_bfloat162 c23 = *reinterpret_cast<const __nv_bfloat162*>(&c.y);
    const float2 f01 = __bfloat1622float2(c01);
    const float2 f23 = __bfloat1622float2(c23);
    d0 = fmaf(f01.x, p.x, fmaf(f01.y, p.y, d0));
    d1 = fmaf(f23.x, p.z, fmaf(f23.y, p.w, d1));
}

// R13 row kernel verbatim (total 29.184us, reproduced 3x): depth-3 pipeline,
// pred streamed via __ldcs (read-once), weights via __ldg, occ-4 / 64 regs.
template <int CN>
__global__ void __launch_bounds__(256, 4)
row_loss_kernel(const float* __restrict__ pred,
                const int*   __restrict__ tgt_raw,
                float* __restrict__ out,
                int Bn, float invB)
{
    constexpr int NVEC = CN / 4;                  // 250
    constexpr int FULL_ITERS = NVEC / 32;         // 7
    constexpr int TAIL = NVEC - FULL_ITERS * 32;  // 26
    constexpr int NITER = FULL_ITERS + 1;         // 8 (incl. predicated tail)

    const int tid  = threadIdx.x;
    const int wid  = tid >> 5;
    const int lane = tid & 31;
    const int row  = blockIdx.x * WARPS_PER_BLOCK + wid;

    // int64 vs int32 target detection (odd 32-bit words all zero => int64).
    const bool is64 = ((tgt_raw[1] | tgt_raw[3] | tgt_raw[5] | tgt_raw[7]) == 0);

    float row_loss = 0.0f;

    if (row < Bn) {
        const int t = is64 ? tgt_raw[2 * row] : tgt_raw[row];

        const float4* prow = reinterpret_cast<const float4*>(pred + (size_t)row * CN);
        const uint2*  crow = reinterpret_cast<const uint2*>(g_pad + (size_t)t * CN);

        // Early target-pred load: issued before the PDL gate, overlaps prep.
        float pt = 0.0f;
        if (lane == 0) pt = __ldcs(pred + (size_t)row * CN + t);

        // PDL gate: wait until the prep grid has published g_pad. pred loads
        // above are already in flight; only weight reads need this ordering.
#if __CUDA_ARCH__ >= 900
        cudaGridDependencySynchronize();
#endif

        float s0 = 0.f, s1 = 0.f, d0 = 0.f, d1 = 0.f;

        // Depth-3 software pipeline; pred streamed (.cs, read once), weights
        // cached (.nc, reused ~33x per class chip-wide).
        float4 p[3];
        uint2  c[3];
#pragma unroll
        for (int k = 0; k < 2; k++) {
            p[k] = __ldcs(prow + lane + k * 32);
            c[k] = __ldg(crow + lane + k * 32);
        }
#pragma unroll
        for (int k = 2; k < NITER; k++) {
            const int slot = k % 3;
            if (k < FULL_ITERS || lane < TAIL) {
                p[slot] = __ldcs(prow + lane + k * 32);
                c[slot] = __ldg(crow + lane + k * 32);
            } else {
                p[slot] = make_float4(-1e30f, -1e30f, -1e30f, -1e30f);  // exp->0
                c[slot] = make_uint2(0u, 0u);
            }
            consume4(p[(k - 2) % 3], c[(k - 2) % 3], s0, s1, d0, d1);
        }
        consume4(p[(NITER - 2) % 3], c[(NITER - 2) % 3], s0, s1, d0, d1);
        consume4(p[(NITER - 1) % 3], c[(NITER - 1) % 3], s0, s1, d0, d1);

        float s   = s0 + s1;
        float dot = d0 + d1;

        const unsigned FULL = 0xffffffffu;
#pragma unroll
        for (int off = 16; off; off >>= 1) {
            s   += __shfl_down_sync(FULL, s,   off);
            dot += __shfl_down_sync(FULL, dot, off);
        }

        if (lane == 0)
            row_loss = __logf(s) - kConfidence * pt - dot;   // dot pre-scaled by 0.1/A
    } else {
#if __CUDA_ARCH__ >= 900
        cudaGridDependencySynchronize();
#endif
    }

    __shared__ float sh[WARPS_PER_BLOCK];
    if (lane == 0) sh[wid] = row_loss;
    __syncthreads();

    if (tid == 0) {
        float acc = sh[0];
#pragma unroll
        for (int w = 1; w < WARPS_PER_BLOCK; w++) acc += sh[w];
        atomicAdd(out, acc * invB);
    }
}

// Generic fallback for unexpected C (runtime trip count).
__global__ void __launch_bounds__(256, 4)
row_loss_kernel_generic(const float* __restrict__ pred,
                        const int*   __restrict__ tgt_raw,
                        float* __restrict__ out,
                        int Bn, int Cn, float invB)
{
    const int tid  = threadIdx.x;
    const int wid  = tid >> 5;
    const int lane = tid & 31;
    const int row  = blockIdx.x * WARPS_PER_BLOCK + wid;
    const bool is64 = ((tgt_raw[1] | tgt_raw[3] | tgt_raw[5] | tgt_raw[7]) == 0);

    float row_loss = 0.0f;
    if (row < Bn) {
        const int t = is64 ? tgt_raw[2 * row] : tgt_raw[row];
        const float4* prow = reinterpret_cast<const float4*>(pred + (size_t)row * Cn);
        const uint2*  crow = reinterpret_cast<const uint2*>(g_pad + (size_t)t * Cn);
        const int nvec = Cn >> 2;
        float s0 = 0.f, s1 = 0.f, d0 = 0.f, d1 = 0.f;
#pragma unroll 4
        for (int j = lane; j < nvec; j += 32) {
            const float4 p4 = __ldg(prow + j);
            const uint2  c4 = __ldg(crow + j);
            consume4(p4, c4, s0, s1, d0, d1);
        }
        float s = s0 + s1, dot = d0 + d1;
        const unsigned FULL = 0xffffffffu;
#pragma unroll
        for (int off = 16; off; off >>= 1) {
            s   += __shfl_down_sync(FULL, s,   off);
            dot += __shfl_down_sync(FULL, dot, off);
        }
        if (lane == 0) {
            const float pt = __ldg(pred + (size_t)row * Cn + t);
            row_loss = __logf(s) - kConfidence * pt - dot;
        }
    }
    __shared__ float sh[WARPS_PER_BLOCK];
    if (lane == 0) sh[wid] = row_loss;
    __syncthreads();
    if (tid == 0) {
        float acc = sh[0];
#pragma unroll
        for (int w = 1; w < WARPS_PER_BLOCK; w++) acc += sh[w];
        atomicAdd(out, acc * invB);
    }
}

extern "C" void kernel_launch(void* const* d_in, const int* in_sizes, int n_in,
                              void* d_out, int out_size) {
    const float* pred      = (const float*)d_in[0];
    const int*   tgt_raw   = (const int*)d_in[1];
    const float* confusion = (const float*)d_in[2];

    const int Bn = in_sizes[1];          // 32768 rows
    const int Cn = in_sizes[0] / Bn;     // 1000 classes

    float* out = (float*)d_out;
    prep_conf_kernel<<<Cn, 256>>>(confusion, out, Cn);

    const float invB = 1.0f / (float)Bn;
    const int grid = (Bn + WARPS_PER_BLOCK - 1) / WARPS_PER_BLOCK;   // 4096

    if (Cn == 1000) {
        // PDL launch: row kernel overlaps prep's tail; weight reads are gated
        // in-kernel by cudaGridDependencySynchronize().
        cudaLaunchConfig_t cfg = {};
        cfg.gridDim  = dim3(grid);
        cfg.blockDim = dim3(256);
        cfg.dynamicSmemBytes = 0;
        cfg.stream = 0;
        cudaLaunchAttribute attrs[1];
        attrs[0].id = cudaLaunchAttributeProgrammaticStreamSerialization;
        attrs[0].val.programmaticStreamSerializationAllowed = 1;
        cfg.attrs = attrs;
        cfg.numAttrs = 1;

        cudaError_t e = cudaLaunchKernelEx(&cfg, row_loss_kernel<1000>,
                                           pred, tgt_raw, out, Bn, invB);
        if (e != cudaSuccess) {
            (void)cudaGetLastError();   // clear, fall back to plain launch
            row_loss_kernel<1000><<<grid, 256>>>(pred, tgt_raw, out, Bn, invB);
        }
    } else {
        row_loss_kernel_generic<<<grid, 256>>>(pred, tgt_raw, out, Bn, Cn, invB);
    }
}